// round 4
// baseline (speedup 1.0000x reference)
#include <cuda_runtime.h>
#include <math.h>

#define B_SZ 1024
#define L_SZ 110
#define D_SZ 512
#define WPAST 10
#define WFUT 10
#define M_TOT (B_SZ * L_SZ)   // 112640

// scratch: att[b,l,d] = sum_e W[d,e] * nf[b,l,e]   (231 MB)
__device__ float g_att[(size_t)M_TOT * D_SZ];

// ---------------------------------------------------------------------------
// Kernel 1: C[m,d] = sum_e A[m,e] * W[d,e]   (NT GEMM, both K-major)
// 128x128 tile, BK=16, 256 threads, 8x8 microtile.
// ---------------------------------------------------------------------------
__global__ __launch_bounds__(256) void edgeatt_gemm(
    const float* __restrict__ A,   // [M_TOT, 512]
    const float* __restrict__ W)   // [512, 512]
{
    const int BK = 16;
    __shared__ float As[BK][128];
    __shared__ float Bs[BK][128];

    const int t  = threadIdx.x;
    const int tx = t & 15;          // 0..15  (N direction)
    const int ty = t >> 4;          // 0..15  (M direction)
    const int m0 = blockIdx.y * 128;
    const int n0 = blockIdx.x * 128;

    float acc[8][8];
#pragma unroll
    for (int i = 0; i < 8; i++)
#pragma unroll
        for (int j = 0; j < 8; j++) acc[i][j] = 0.f;

    for (int k0 = 0; k0 < D_SZ; k0 += BK) {
        // load 128x16 tiles of A and W, store K-major (transposed) into smem
#pragma unroll
        for (int i = 0; i < 2; i++) {
            int idx = t + i * 256;          // 0..511
            int row = idx >> 2;             // 0..127
            int col = (idx & 3) * 4;        // 0,4,8,12
            float4 va = *(const float4*)&A[(size_t)(m0 + row) * D_SZ + k0 + col];
            As[col + 0][row] = va.x; As[col + 1][row] = va.y;
            As[col + 2][row] = va.z; As[col + 3][row] = va.w;
            float4 vb = *(const float4*)&W[(size_t)(n0 + row) * D_SZ + k0 + col];
            Bs[col + 0][row] = vb.x; Bs[col + 1][row] = vb.y;
            Bs[col + 2][row] = vb.z; Bs[col + 3][row] = vb.w;
        }
        __syncthreads();

#pragma unroll
        for (int k = 0; k < BK; k++) {
            float a[8], b[8];
            *(float4*)&a[0] = *(const float4*)&As[k][ty * 8 + 0];
            *(float4*)&a[4] = *(const float4*)&As[k][ty * 8 + 4];
            *(float4*)&b[0] = *(const float4*)&Bs[k][tx * 8 + 0];
            *(float4*)&b[4] = *(const float4*)&Bs[k][tx * 8 + 4];
#pragma unroll
            for (int i = 0; i < 8; i++)
#pragma unroll
                for (int j = 0; j < 8; j++)
                    acc[i][j] = fmaf(a[i], b[j], acc[i][j]);
        }
        __syncthreads();
    }

#pragma unroll
    for (int i = 0; i < 8; i++) {
        size_t base = (size_t)(m0 + ty * 8 + i) * D_SZ + n0 + tx * 8;
        float4 v0 = make_float4(acc[i][0], acc[i][1], acc[i][2], acc[i][3]);
        float4 v1 = make_float4(acc[i][4], acc[i][5], acc[i][6], acc[i][7]);
        *(float4*)&g_att[base]     = v0;
        *(float4*)&g_att[base + 4] = v1;
    }
}

// ---------------------------------------------------------------------------
// Kernel 2: banded scores + masked softmax + full-row output write.
// One warp per (b, j). Lanes split K for the dots, then hold window
// probabilities (lane = window index) for the row write via shfl.
// ---------------------------------------------------------------------------
__global__ __launch_bounds__(256) void edgeatt_band_softmax(
    const float* __restrict__ nf,     // [B, L, 512]
    const int*   __restrict__ tlen,   // [B]
    float*       __restrict__ out)    // [B, L, 110]
{
    const int b    = blockIdx.y;
    const int warp = threadIdx.x >> 5;
    const int lane = threadIdx.x & 31;
    const int j    = blockIdx.x * 8 + warp;
    if (j >= L_SZ) return;

    const int len = tlen[b];
    float* orow = out + ((size_t)b * L_SZ + j) * 110;

    if (j >= len) {
        // fully masked row -> all zeros (warp-uniform branch)
#pragma unroll
        for (int c0 = 0; c0 < 128; c0 += 32) {
            int c = c0 + lane;
            if (c < 110) orow[c] = 0.f;
        }
        return;
    }

    // cache this j's feature row: lane owns k = lane*16 .. lane*16+15
    const float* xr = nf + ((size_t)b * L_SZ + j) * D_SZ;
    float4 xf[4];
#pragma unroll
    for (int q = 0; q < 4; q++)
        xf[q] = *(const float4*)&xr[lane * 16 + q * 4];

    const int lo = j - WPAST;            // window start (may be negative)
    float myscore = 0.f;                 // lane wi holds score of window idx wi

#pragma unroll 1
    for (int wi = 0; wi < WPAST + WFUT + 1; wi++) {
        int l = lo + wi;                 // warp-uniform
        if (l < 0 || l >= len) continue; // warp-uniform branch
        const float* ar = g_att + ((size_t)b * L_SZ + l) * D_SZ;
        float s = 0.f;
#pragma unroll
        for (int q = 0; q < 4; q++) {
            float4 av = *(const float4*)&ar[lane * 16 + q * 4];
            s = fmaf(av.x, xf[q].x, s);
            s = fmaf(av.y, xf[q].y, s);
            s = fmaf(av.z, xf[q].z, s);
            s = fmaf(av.w, xf[q].w, s);
        }
#pragma unroll
        for (int off = 16; off > 0; off >>= 1)
            s += __shfl_xor_sync(0xffffffffu, s, off);
        if (lane == wi) myscore = s;
    }

    // masked softmax over lanes 0..20 (window positions)
    const int  l_of_lane = lo + lane;
    const bool valid = (lane < WPAST + WFUT + 1) && (l_of_lane >= 0) && (l_of_lane < len);

    float v = valid ? myscore : -INFINITY;
    float m = v;
#pragma unroll
    for (int off = 16; off > 0; off >>= 1)
        m = fmaxf(m, __shfl_xor_sync(0xffffffffu, m, off));
    float p = valid ? expf(v - m) : 0.f;
    float sum = p;
#pragma unroll
    for (int off = 16; off > 0; off >>= 1)
        sum += __shfl_xor_sync(0xffffffffu, sum, off);
    float prob = valid ? (p / sum) : 0.f;   // l=j is always valid -> sum > 0

    // write the full 110-column row; fetch band probs cross-lane.
    // Loop trip count is warp-uniform (4 iters for all lanes); only the
    // store is predicated, so every __shfl_sync is executed by all 32 lanes.
#pragma unroll
    for (int c0 = 0; c0 < 128; c0 += 32) {
        int c   = c0 + lane;
        int wi  = c - lo;                              // window index of column c
        int src = (wi >= 0 && wi < 32) ? wi : 31;      // lane 31 always holds 0
        float val = __shfl_sync(0xffffffffu, prob, src);
        if (wi < 0 || wi >= 32) val = 0.f;
        if (c < 110) orow[c] = val;
    }
}

// ---------------------------------------------------------------------------
extern "C" void kernel_launch(void* const* d_in, const int* in_sizes, int n_in,
                              void* d_out, int out_size)
{
    const float* nf   = (const float*)d_in[0];   // node_features [1024,110,512]
    const float* W    = (const float*)d_in[1];   // weight [512,512]
    const int*   tlen = (const int*)d_in[2];     // text_len [1024]
    float* out = (float*)d_out;

    dim3 g1(D_SZ / 128, M_TOT / 128);            // (4, 880)
    edgeatt_gemm<<<g1, 256>>>(nf, W);

    dim3 g2((L_SZ + 7) / 8, B_SZ);               // (14, 1024)
    edgeatt_band_softmax<<<g2, 256>>>(nf, tlen, out);
}

// round 7
// speedup vs baseline: 1.7301x; 1.7301x over previous
#include <cuda_runtime.h>
#include <cuda_fp16.h>
#include <math.h>
#include <stdint.h>

#define B_SZ 1024
#define L_SZ 110
#define D_SZ 512
#define WPAST 10
#define WFUT 10
#define M_TOT (B_SZ * L_SZ)   // 112640

// ---------------- device scratch (allocation-guard-safe) -------------------
__device__ float  g_att[(size_t)M_TOT * D_SZ];     // 231 MB fp32
__device__ __half g_Ahi[(size_t)M_TOT * D_SZ];     // 115 MB
__device__ __half g_Alo[(size_t)M_TOT * D_SZ];     // 115 MB
__device__ __half g_Whi[D_SZ * D_SZ];
__device__ __half g_Wlo[D_SZ * D_SZ];

__device__ __forceinline__ uint32_t smem_u32(const void* p) {
    uint32_t a;
    asm("{ .reg .u64 t; cvta.to.shared.u64 t, %1; cvt.u32.u64 %0, t; }"
        : "=r"(a) : "l"(p));
    return a;
}

#define LDSM4(d, addr) \
    asm volatile("ldmatrix.sync.aligned.m8n8.x4.shared.b16 {%0,%1,%2,%3}, [%4];" \
        : "=r"((d)[0]), "=r"((d)[1]), "=r"((d)[2]), "=r"((d)[3]) : "r"(addr))

#define MMA_16816(d, a, b) \
    asm volatile("mma.sync.aligned.m16n8k16.row.col.f32.f16.f16.f32 " \
        "{%0,%1,%2,%3},{%4,%5,%6,%7},{%8,%9},{%0,%1,%2,%3};" \
        : "+f"((d)[0]), "+f"((d)[1]), "+f"((d)[2]), "+f"((d)[3]) \
        : "r"((a)[0]), "r"((a)[1]), "r"((a)[2]), "r"((a)[3]), \
          "r"((b)[0]), "r"((b)[1]))

// ---------------------------------------------------------------------------
// fp16 hi/lo split kernels
// ---------------------------------------------------------------------------
__global__ __launch_bounds__(256) void split_A(const float* __restrict__ src) {
    size_t i = (size_t)blockIdx.x * blockDim.x + threadIdx.x;   // float4 index
    const size_t n4 = (size_t)M_TOT * D_SZ / 4;
    if (i >= n4) return;
    float4 v = ((const float4*)src)[i];
    __half h0 = __float2half_rn(v.x), h1 = __float2half_rn(v.y);
    __half h2 = __float2half_rn(v.z), h3 = __float2half_rn(v.w);
    __half l0 = __float2half_rn(v.x - __half2float(h0));
    __half l1 = __float2half_rn(v.y - __half2float(h1));
    __half l2 = __float2half_rn(v.z - __half2float(h2));
    __half l3 = __float2half_rn(v.w - __half2float(h3));
    ((__half2*)g_Ahi)[i * 2 + 0] = __halves2half2(h0, h1);
    ((__half2*)g_Ahi)[i * 2 + 1] = __halves2half2(h2, h3);
    ((__half2*)g_Alo)[i * 2 + 0] = __halves2half2(l0, l1);
    ((__half2*)g_Alo)[i * 2 + 1] = __halves2half2(l2, l3);
}
__global__ __launch_bounds__(256) void split_W(const float* __restrict__ src) {
    size_t i = (size_t)blockIdx.x * blockDim.x + threadIdx.x;
    const size_t n4 = (size_t)D_SZ * D_SZ / 4;
    if (i >= n4) return;
    float4 v = ((const float4*)src)[i];
    __half h0 = __float2half_rn(v.x), h1 = __float2half_rn(v.y);
    __half h2 = __float2half_rn(v.z), h3 = __float2half_rn(v.w);
    __half l0 = __float2half_rn(v.x - __half2float(h0));
    __half l1 = __float2half_rn(v.y - __half2float(h1));
    __half l2 = __float2half_rn(v.z - __half2float(h2));
    __half l3 = __float2half_rn(v.w - __half2float(h3));
    ((__half2*)g_Whi)[i * 2 + 0] = __halves2half2(h0, h1);
    ((__half2*)g_Whi)[i * 2 + 1] = __halves2half2(h2, h3);
    ((__half2*)g_Wlo)[i * 2 + 0] = __halves2half2(l0, l1);
    ((__half2*)g_Wlo)[i * 2 + 1] = __halves2half2(l2, l3);
}

// ---------------------------------------------------------------------------
// HMMA GEMM: att[m, n] = sum_k A[m,k] * W[n,k]   (split fp16, fp32 accum)
// CTA 128x128, 8 warps of 64x32 (wm in {0,1}, wn in {0..3}).
// K chunks of 32 halves (64B rows, padded to 80B stride -> ldmatrix
// conflict-free). Double-buffered smem, LDG->reg->STS software pipeline.
// 3 passes per k16 step: Ahi*Whi + Ahi*Wlo + Alo*Whi.
// ---------------------------------------------------------------------------
#define KC 32
#define ROWB 80
#define TILE_B (128 * ROWB)          // 10240
#define OFF_AHI 0
#define OFF_ALO (1 * TILE_B)
#define OFF_WHI (2 * TILE_B)
#define OFF_WLO (3 * TILE_B)
#define STAGE   (4 * TILE_B)         // 40960
#define GEMM_SMEM (2 * STAGE)        // 81920
#define NCHUNK (D_SZ / KC)           // 16

__global__ __launch_bounds__(256) void edgeatt_gemm_hmma() {
    extern __shared__ char smg[];
    const uint32_t sb = smem_u32(smg);
    const int tid  = threadIdx.x;
    const int wid  = tid >> 5;
    const int lane = tid & 31;
    const int wm = wid >> 2;            // 0..1
    const int wn = wid & 3;             // 0..3
    const int m0 = blockIdx.y * 128;
    const int n0 = blockIdx.x * 128;

    float acc[4][4][4];
#pragma unroll
    for (int i = 0; i < 4; i++)
#pragma unroll
        for (int j = 0; j < 4; j++)
#pragma unroll
            for (int q = 0; q < 4; q++) acc[i][j][q] = 0.f;

    // gmem/smem load mapping: 512 16B-chunks per matrix, 2 per thread
    size_t aoff[2], woff[2];
    int    soff[2];
#pragma unroll
    for (int i = 0; i < 2; i++) {
        int idx = tid + i * 256;
        int row = idx >> 2, ch = idx & 3;
        aoff[i] = (size_t)(m0 + row) * D_SZ + ch * 8;
        woff[i] = (size_t)(n0 + row) * D_SZ + ch * 8;
        soff[i] = row * ROWB + ch * 16;
    }

    uint4 vAh[2], vAl[2], vWh[2], vWl[2];

    // prologue: load chunk 0, store to buf 0
#pragma unroll
    for (int i = 0; i < 2; i++) {
        vAh[i] = *(const uint4*)(g_Ahi + aoff[i]);
        vAl[i] = *(const uint4*)(g_Alo + aoff[i]);
        vWh[i] = *(const uint4*)(g_Whi + woff[i]);
        vWl[i] = *(const uint4*)(g_Wlo + woff[i]);
    }
#pragma unroll
    for (int i = 0; i < 2; i++) {
        *(uint4*)(smg + OFF_AHI + soff[i]) = vAh[i];
        *(uint4*)(smg + OFF_ALO + soff[i]) = vAl[i];
        *(uint4*)(smg + OFF_WHI + soff[i]) = vWh[i];
        *(uint4*)(smg + OFF_WLO + soff[i]) = vWl[i];
    }
    __syncthreads();

    const int g = lane >> 3, r = lane & 7;
    const int arow = wm * 64 + ((g & 1) << 3) + r;       // + mt*16
    const int brow = wn * 32 + ((g >> 1) << 3) + r;      // + bt*16
    const int akc  = (g >> 1);                           // + ks*2
    const int bkc  = (g & 1);

    for (int c = 0; c < NCHUNK; c++) {
        const int buf = c & 1;
        if (c + 1 < NCHUNK) {
            size_t kadd = (size_t)(c + 1) * KC;
#pragma unroll
            for (int i = 0; i < 2; i++) {
                vAh[i] = *(const uint4*)(g_Ahi + aoff[i] + kadd);
                vAl[i] = *(const uint4*)(g_Alo + aoff[i] + kadd);
                vWh[i] = *(const uint4*)(g_Whi + woff[i] + kadd);
                vWl[i] = *(const uint4*)(g_Wlo + woff[i] + kadd);
            }
        }

        const uint32_t abase = sb + buf * STAGE;
#pragma unroll
        for (int ks = 0; ks < 2; ks++) {
            uint32_t ah[4][4], al[4][4], bh[2][4], bl[2][4];
#pragma unroll
            for (int mt = 0; mt < 4; mt++) {
                uint32_t ad = abase + OFF_AHI + (arow + mt * 16) * ROWB
                            + (ks * 2 + akc) * 16;
                LDSM4(ah[mt], ad);
                LDSM4(al[mt], ad + (OFF_ALO - OFF_AHI));
            }
#pragma unroll
            for (int bt = 0; bt < 2; bt++) {
                uint32_t bd = abase + OFF_WHI + (brow + bt * 16) * ROWB
                            + (ks * 2 + bkc) * 16;
                LDSM4(bh[bt], bd);
                LDSM4(bl[bt], bd + (OFF_WLO - OFF_WHI));
            }
#pragma unroll
            for (int mt = 0; mt < 4; mt++)
#pragma unroll
                for (int nt = 0; nt < 4; nt++) {
                    const int bt = nt >> 1, h = (nt & 1) * 2;
                    MMA_16816(acc[mt][nt], ah[mt], &bh[bt][h]);
                    MMA_16816(acc[mt][nt], ah[mt], &bl[bt][h]);
                    MMA_16816(acc[mt][nt], al[mt], &bh[bt][h]);
                }
        }

        if (c + 1 < NCHUNK) {
            char* p = smg + (buf ^ 1) * STAGE;
#pragma unroll
            for (int i = 0; i < 2; i++) {
                *(uint4*)(p + OFF_AHI + soff[i]) = vAh[i];
                *(uint4*)(p + OFF_ALO + soff[i]) = vAl[i];
                *(uint4*)(p + OFF_WHI + soff[i]) = vWh[i];
                *(uint4*)(p + OFF_WLO + soff[i]) = vWl[i];
            }
        }
        __syncthreads();
    }

    // epilogue: C fragment -> g_att
    const int er = lane >> 2, ec = (lane & 3) * 2;
#pragma unroll
    for (int mt = 0; mt < 4; mt++) {
        const int row = m0 + wm * 64 + mt * 16 + er;
#pragma unroll
        for (int nt = 0; nt < 4; nt++) {
            const int col = n0 + wn * 32 + nt * 8 + ec;
            *(float2*)&g_att[(size_t)row * D_SZ + col] =
                make_float2(acc[mt][nt][0], acc[mt][nt][1]);
            *(float2*)&g_att[(size_t)(row + 8) * D_SZ + col] =
                make_float2(acc[mt][nt][2], acc[mt][nt][3]);
        }
    }
}

// ---------------------------------------------------------------------------
// Band + softmax: CTA of 8 warps handles j0..j0+7 for one b.
// Cooperative smem tile of att rows [max(j0-10,0), min(j0+17, len-1)].
// ---------------------------------------------------------------------------
#define JB 8
#define BAND_ROWS 28
#define BAND_SMEM (BAND_ROWS * D_SZ * 4)   // 57344

__global__ __launch_bounds__(256) void edgeatt_band_softmax(
    const float* __restrict__ nf,     // [B, L, 512]
    const int*   __restrict__ tlen,   // [B]
    float*       __restrict__ out)    // [B, L, 110]
{
    extern __shared__ float s_att[];  // [BAND_ROWS][512]
    const int b    = blockIdx.y;
    const int j0   = blockIdx.x * JB;
    const int warp = threadIdx.x >> 5;
    const int lane = threadIdx.x & 31;
    const int tid  = threadIdx.x;
    const int len  = tlen[b];

    // cooperative load of needed att rows (only l < len ever used)
    const int rlo   = max(j0 - WPAST, 0);
    const int rhi   = min(min(j0 + JB - 1 + WFUT, L_SZ - 1), len - 1);
    const int nrows = rhi - rlo + 1;                    // may be <= 0
    if (nrows > 0) {
        const float* gsrc = g_att + ((size_t)b * L_SZ + rlo) * D_SZ;
        for (int idx = tid; idx < nrows * (D_SZ / 4); idx += 256) {
            int row = idx >> 7, q = idx & 127;
            *(float4*)&s_att[row * D_SZ + q * 4] =
                *(const float4*)&gsrc[(size_t)row * D_SZ + q * 4];
        }
    }
    __syncthreads();

    const int j = j0 + warp;
    if (j >= L_SZ) return;
    float* orow = out + ((size_t)b * L_SZ + j) * 110;

    if (j >= len) {
#pragma unroll
        for (int c0 = 0; c0 < 128; c0 += 32) {
            int c = c0 + lane;
            if (c < 110) orow[c] = 0.f;
        }
        return;
    }

    const float* xr = nf + ((size_t)b * L_SZ + j) * D_SZ;
    float4 xf[4];
#pragma unroll
    for (int q = 0; q < 4; q++)
        xf[q] = *(const float4*)&xr[lane * 16 + q * 4];

    const int lo = j - WPAST;
    float myscore = 0.f;

#pragma unroll 1
    for (int wi = 0; wi < WPAST + WFUT + 1; wi++) {
        int l = lo + wi;                     // warp-uniform
        if (l < 0 || l >= len) continue;
        const float* ar = &s_att[(l - rlo) * D_SZ];
        float s = 0.f;
#pragma unroll
        for (int q = 0; q < 4; q++) {
            float4 av = *(const float4*)&ar[lane * 16 + q * 4];
            s = fmaf(av.x, xf[q].x, s);
            s = fmaf(av.y, xf[q].y, s);
            s = fmaf(av.z, xf[q].z, s);
            s = fmaf(av.w, xf[q].w, s);
        }
#pragma unroll
        for (int off = 16; off > 0; off >>= 1)
            s += __shfl_xor_sync(0xffffffffu, s, off);
        if (lane == wi) myscore = s;
    }

    const int  l_of_lane = lo + lane;
    const bool valid = (lane < WPAST + WFUT + 1) && (l_of_lane >= 0) && (l_of_lane < len);

    float v = valid ? myscore : -INFINITY;
    float m = v;
#pragma unroll
    for (int off = 16; off > 0; off >>= 1)
        m = fmaxf(m, __shfl_xor_sync(0xffffffffu, m, off));
    float p = valid ? expf(v - m) : 0.f;
    float sum = p;
#pragma unroll
    for (int off = 16; off > 0; off >>= 1)
        sum += __shfl_xor_sync(0xffffffffu, sum, off);
    float prob = valid ? (p / sum) : 0.f;

#pragma unroll
    for (int c0 = 0; c0 < 128; c0 += 32) {
        int c   = c0 + lane;
        int wi  = c - lo;
        int src = (wi >= 0 && wi < 32) ? wi : 31;
        float val = __shfl_sync(0xffffffffu, prob, src);
        if (wi < 0 || wi >= 32) val = 0.f;
        if (c < 110) orow[c] = val;
    }
}

// ---------------------------------------------------------------------------
extern "C" void kernel_launch(void* const* d_in, const int* in_sizes, int n_in,
                              void* d_out, int out_size)
{
    const float* nf   = (const float*)d_in[0];
    const float* W    = (const float*)d_in[1];
    const int*   tlen = (const int*)d_in[2];
    float* out = (float*)d_out;

    static int attr_done = 0;
    if (!attr_done) {
        cudaFuncSetAttribute(edgeatt_gemm_hmma,
                             cudaFuncAttributeMaxDynamicSharedMemorySize, GEMM_SMEM);
        cudaFuncSetAttribute(edgeatt_band_softmax,
                             cudaFuncAttributeMaxDynamicSharedMemorySize, BAND_SMEM);
        attr_done = 1;
    }

    split_A<<<(M_TOT * D_SZ / 4 + 255) / 256, 256>>>(nf);
    split_W<<<(D_SZ * D_SZ / 4 + 255) / 256, 256>>>(W);

    dim3 gg(D_SZ / 128, M_TOT / 128);   // (4, 880)
    edgeatt_gemm_hmma<<<gg, 256, GEMM_SMEM>>>();

    dim3 gb((L_SZ + JB - 1) / JB, B_SZ); // (14, 1024)
    edgeatt_band_softmax<<<gb, 256, BAND_SMEM>>>(nf, tlen, out);
}

// round 8
// speedup vs baseline: 3.0138x; 1.7420x over previous
#include <cuda_runtime.h>
#include <cuda_fp16.h>
#include <math.h>
#include <stdint.h>

#define B_SZ 1024
#define L_SZ 110
#define D_SZ 512
#define WPAST 10
#define WFUT 10
#define M_TOT (B_SZ * L_SZ)   // 112640

// ---------------- device scratch (allocation-guard-safe) -------------------
__device__ float  g_att[(size_t)M_TOT * D_SZ];     // compact att rows
__device__ __half g_Ahi[(size_t)M_TOT * D_SZ];
__device__ __half g_Alo[(size_t)M_TOT * D_SZ];
__device__ __half g_Whi[D_SZ * D_SZ];
__device__ __half g_Wlo[D_SZ * D_SZ];
__device__ int    g_cbase[B_SZ + 1];               // exclusive prefix of len; [B]=Mc
__device__ int    g_rowmap[M_TOT];                 // compact row -> absolute row

__device__ __forceinline__ uint32_t smem_u32(const void* p) {
    uint32_t a;
    asm("{ .reg .u64 t; cvta.to.shared.u64 t, %1; cvt.u32.u64 %0, t; }"
        : "=r"(a) : "l"(p));
    return a;
}

#define LDSM4(d, addr) \
    asm volatile("ldmatrix.sync.aligned.m8n8.x4.shared.b16 {%0,%1,%2,%3}, [%4];" \
        : "=r"((d)[0]), "=r"((d)[1]), "=r"((d)[2]), "=r"((d)[3]) : "r"(addr))

#define MMA_16816(d, a, b) \
    asm volatile("mma.sync.aligned.m16n8k16.row.col.f32.f16.f16.f32 " \
        "{%0,%1,%2,%3},{%4,%5,%6,%7},{%8,%9},{%0,%1,%2,%3};" \
        : "+f"((d)[0]), "+f"((d)[1]), "+f"((d)[2]), "+f"((d)[3]) \
        : "r"((a)[0]), "r"((a)[1]), "r"((a)[2]), "r"((a)[3]), \
          "r"((b)[0]), "r"((b)[1]))

// ---------------------------------------------------------------------------
// Prefix scan of text_len (one block, 1024 threads, Hillis-Steele)
// ---------------------------------------------------------------------------
__global__ __launch_bounds__(1024) void scan_len(const int* __restrict__ tlen) {
    __shared__ int s[B_SZ];
    const int t = threadIdx.x;
    s[t] = tlen[t];
    __syncthreads();
    for (int off = 1; off < B_SZ; off <<= 1) {
        int v = (t >= off) ? s[t - off] : 0;
        __syncthreads();
        s[t] += v;
        __syncthreads();
    }
    if (t == 0) g_cbase[0] = 0;
    g_cbase[t + 1] = s[t];
}

__global__ __launch_bounds__(128) void fill_rowmap(const int* __restrict__ tlen) {
    const int b    = blockIdx.x;
    const int len  = tlen[b];
    const int base = g_cbase[b];
    for (int l = threadIdx.x; l < len; l += 128)
        g_rowmap[base + l] = b * L_SZ + l;
}

// ---------------------------------------------------------------------------
// fp16 hi/lo split kernels
// ---------------------------------------------------------------------------
__global__ __launch_bounds__(256) void split_A(const float* __restrict__ src) {
    size_t i = (size_t)blockIdx.x * blockDim.x + threadIdx.x;
    const size_t n4 = (size_t)M_TOT * D_SZ / 4;
    if (i >= n4) return;
    float4 v = ((const float4*)src)[i];
    __half h0 = __float2half_rn(v.x), h1 = __float2half_rn(v.y);
    __half h2 = __float2half_rn(v.z), h3 = __float2half_rn(v.w);
    __half l0 = __float2half_rn(v.x - __half2float(h0));
    __half l1 = __float2half_rn(v.y - __half2float(h1));
    __half l2 = __float2half_rn(v.z - __half2float(h2));
    __half l3 = __float2half_rn(v.w - __half2float(h3));
    ((__half2*)g_Ahi)[i * 2 + 0] = __halves2half2(h0, h1);
    ((__half2*)g_Ahi)[i * 2 + 1] = __halves2half2(h2, h3);
    ((__half2*)g_Alo)[i * 2 + 0] = __halves2half2(l0, l1);
    ((__half2*)g_Alo)[i * 2 + 1] = __halves2half2(l2, l3);
}
__global__ __launch_bounds__(256) void split_W(const float* __restrict__ src) {
    size_t i = (size_t)blockIdx.x * blockDim.x + threadIdx.x;
    const size_t n4 = (size_t)D_SZ * D_SZ / 4;
    if (i >= n4) return;
    float4 v = ((const float4*)src)[i];
    __half h0 = __float2half_rn(v.x), h1 = __float2half_rn(v.y);
    __half h2 = __float2half_rn(v.z), h3 = __float2half_rn(v.w);
    __half l0 = __float2half_rn(v.x - __half2float(h0));
    __half l1 = __float2half_rn(v.y - __half2float(h1));
    __half l2 = __float2half_rn(v.z - __half2float(h2));
    __half l3 = __float2half_rn(v.w - __half2float(h3));
    ((__half2*)g_Whi)[i * 2 + 0] = __halves2half2(h0, h1);
    ((__half2*)g_Whi)[i * 2 + 1] = __halves2half2(h2, h3);
    ((__half2*)g_Wlo)[i * 2 + 0] = __halves2half2(l0, l1);
    ((__half2*)g_Wlo)[i * 2 + 1] = __halves2half2(l2, l3);
}

// ---------------------------------------------------------------------------
// HMMA GEMM over COMPACT rows: att_c[mc, n] = sum_k A[rowmap[mc], k] * W[n, k]
// CTA 128x128, 8 warps of 64x32. K chunks of 32 halves, 80B smem row stride,
// double buffer, LDG->reg->STS pipeline. 3 split-fp16 passes per k16 step.
// ---------------------------------------------------------------------------
#define KC 32
#define ROWB 80
#define TILE_B (128 * ROWB)
#define OFF_AHI 0
#define OFF_ALO (1 * TILE_B)
#define OFF_WHI (2 * TILE_B)
#define OFF_WLO (3 * TILE_B)
#define STAGE   (4 * TILE_B)
#define GEMM_SMEM (2 * STAGE)        // 81920
#define NCHUNK (D_SZ / KC)           // 16

__global__ __launch_bounds__(256) void edgeatt_gemm_hmma() {
    const int Mc = g_cbase[B_SZ];
    const int m0 = blockIdx.y * 128;
    if (m0 >= Mc) return;                       // dead tile: nothing to compute

    extern __shared__ char smg[];
    const uint32_t sb = smem_u32(smg);
    const int tid  = threadIdx.x;
    const int wid  = tid >> 5;
    const int lane = tid & 31;
    const int wm = wid >> 2;
    const int wn = wid & 3;
    const int n0 = blockIdx.x * 128;

    float acc[4][4][4];
#pragma unroll
    for (int i = 0; i < 4; i++)
#pragma unroll
        for (int j = 0; j < 4; j++)
#pragma unroll
            for (int q = 0; q < 4; q++) acc[i][j][q] = 0.f;

    size_t aoff[2], woff[2];
    int    soff[2];
#pragma unroll
    for (int i = 0; i < 2; i++) {
        int idx = tid + i * 256;
        int row = idx >> 2, ch = idx & 3;
        int arow = g_rowmap[min(m0 + row, Mc - 1)];     // gather compact row
        aoff[i] = (size_t)arow * D_SZ + ch * 8;
        woff[i] = (size_t)(n0 + row) * D_SZ + ch * 8;
        soff[i] = row * ROWB + ch * 16;
    }

    uint4 vAh[2], vAl[2], vWh[2], vWl[2];
#pragma unroll
    for (int i = 0; i < 2; i++) {
        vAh[i] = *(const uint4*)(g_Ahi + aoff[i]);
        vAl[i] = *(const uint4*)(g_Alo + aoff[i]);
        vWh[i] = *(const uint4*)(g_Whi + woff[i]);
        vWl[i] = *(const uint4*)(g_Wlo + woff[i]);
    }
#pragma unroll
    for (int i = 0; i < 2; i++) {
        *(uint4*)(smg + OFF_AHI + soff[i]) = vAh[i];
        *(uint4*)(smg + OFF_ALO + soff[i]) = vAl[i];
        *(uint4*)(smg + OFF_WHI + soff[i]) = vWh[i];
        *(uint4*)(smg + OFF_WLO + soff[i]) = vWl[i];
    }
    __syncthreads();

    const int g = lane >> 3, r = lane & 7;
    const int arow = wm * 64 + ((g & 1) << 3) + r;
    const int brow = wn * 32 + ((g >> 1) << 3) + r;
    const int akc  = (g >> 1);
    const int bkc  = (g & 1);

    for (int c = 0; c < NCHUNK; c++) {
        const int buf = c & 1;
        if (c + 1 < NCHUNK) {
            size_t kadd = (size_t)(c + 1) * KC;
#pragma unroll
            for (int i = 0; i < 2; i++) {
                vAh[i] = *(const uint4*)(g_Ahi + aoff[i] + kadd);
                vAl[i] = *(const uint4*)(g_Alo + aoff[i] + kadd);
                vWh[i] = *(const uint4*)(g_Whi + woff[i] + kadd);
                vWl[i] = *(const uint4*)(g_Wlo + woff[i] + kadd);
            }
        }

        const uint32_t abase = sb + buf * STAGE;
#pragma unroll
        for (int ks = 0; ks < 2; ks++) {
            uint32_t ah[4][4], al[4][4], bh[2][4], bl[2][4];
#pragma unroll
            for (int mt = 0; mt < 4; mt++) {
                uint32_t ad = abase + OFF_AHI + (arow + mt * 16) * ROWB
                            + (ks * 2 + akc) * 16;
                LDSM4(ah[mt], ad);
                LDSM4(al[mt], ad + (OFF_ALO - OFF_AHI));
            }
#pragma unroll
            for (int bt = 0; bt < 2; bt++) {
                uint32_t bd = abase + OFF_WHI + (brow + bt * 16) * ROWB
                            + (ks * 2 + bkc) * 16;
                LDSM4(bh[bt], bd);
                LDSM4(bl[bt], bd + (OFF_WLO - OFF_WHI));
            }
#pragma unroll
            for (int mt = 0; mt < 4; mt++)
#pragma unroll
                for (int nt = 0; nt < 4; nt++) {
                    const int bt = nt >> 1, h = (nt & 1) * 2;
                    MMA_16816(acc[mt][nt], ah[mt], &bh[bt][h]);
                    MMA_16816(acc[mt][nt], ah[mt], &bl[bt][h]);
                    MMA_16816(acc[mt][nt], al[mt], &bh[bt][h]);
                }
        }

        if (c + 1 < NCHUNK) {
            char* p = smg + (buf ^ 1) * STAGE;
#pragma unroll
            for (int i = 0; i < 2; i++) {
                *(uint4*)(p + OFF_AHI + soff[i]) = vAh[i];
                *(uint4*)(p + OFF_ALO + soff[i]) = vAl[i];
                *(uint4*)(p + OFF_WHI + soff[i]) = vWh[i];
                *(uint4*)(p + OFF_WLO + soff[i]) = vWl[i];
            }
        }
        __syncthreads();
    }

    // epilogue: compact-row store, predicated on Mc
    const int er = lane >> 2, ec = (lane & 3) * 2;
#pragma unroll
    for (int mt = 0; mt < 4; mt++) {
        const int row = m0 + wm * 64 + mt * 16 + er;
#pragma unroll
        for (int nt = 0; nt < 4; nt++) {
            const int col = n0 + wn * 32 + nt * 8 + ec;
            if (row < Mc)
                *(float2*)&g_att[(size_t)row * D_SZ + col] =
                    make_float2(acc[mt][nt][0], acc[mt][nt][1]);
            if (row + 8 < Mc)
                *(float2*)&g_att[(size_t)(row + 8) * D_SZ + col] =
                    make_float2(acc[mt][nt][2], acc[mt][nt][3]);
        }
    }
}

// ---------------------------------------------------------------------------
// Band + softmax: one warp handles TWO adjacent j rows (j0 even, j1=j0+1).
// Windows overlap 20/21, so one pass over the 22-row union of att rows
// (loaded directly from gmem -> L1) feeds both dot-product sets.
// att is compact: row (b, l) lives at g_att[(cbase[b] + l) * 512].
// ---------------------------------------------------------------------------
__global__ __launch_bounds__(256) void edgeatt_band_softmax(
    const float* __restrict__ nf,     // [B, L, 512]
    const int*   __restrict__ tlen,   // [B]
    float*       __restrict__ out)    // [B, L, 110]
{
    const int b    = blockIdx.y;
    const int warp = threadIdx.x >> 5;
    const int lane = threadIdx.x & 31;
    const int j0   = blockIdx.x * 16 + warp * 2;
    const int j1   = j0 + 1;
    if (j0 >= L_SZ) return;                    // j1 <= 109 whenever j0 <= 108

    const int len  = tlen[b];
    const int base = g_cbase[b];
    float* orow0 = out + ((size_t)b * L_SZ + j0) * 110;
    float* orow1 = out + ((size_t)b * L_SZ + j1) * 110;

    if (j0 >= len) {                           // both rows fully masked
#pragma unroll
        for (int c0 = 0; c0 < 128; c0 += 32) {
            int c = c0 + lane;
            if (c < 110) { orow0[c] = 0.f; orow1[c] = 0.f; }
        }
        return;
    }

    // feature rows for j0 and j1: lane owns k = lane*16 .. lane*16+15
    const float* xr0 = nf + ((size_t)b * L_SZ + j0) * D_SZ;
    const float* xr1 = nf + ((size_t)b * L_SZ + j1) * D_SZ;
    float4 x0[4], x1[4];
#pragma unroll
    for (int q = 0; q < 4; q++) {
        x0[q] = *(const float4*)&xr0[lane * 16 + q * 4];
        x1[q] = *(const float4*)&xr1[lane * 16 + q * 4];
    }

    const int lo = j0 - WPAST;                 // union start; j1 window shifted +1
    float sc0 = 0.f, sc1 = 0.f;                // lane w = window pos w of each j

#pragma unroll 1
    for (int wi = 0; wi < WPAST + WFUT + 2; wi++) {   // 22-row union
        int l = lo + wi;                       // warp-uniform
        if (l < 0 || l >= len) continue;
        const float* ar = g_att + ((size_t)(base + l)) * D_SZ;
        float s0 = 0.f, s1 = 0.f;
#pragma unroll
        for (int q = 0; q < 4; q++) {
            float4 av = *(const float4*)&ar[lane * 16 + q * 4];
            s0 = fmaf(av.x, x0[q].x, s0); s1 = fmaf(av.x, x1[q].x, s1);
            s0 = fmaf(av.y, x0[q].y, s0); s1 = fmaf(av.y, x1[q].y, s1);
            s0 = fmaf(av.z, x0[q].z, s0); s1 = fmaf(av.z, x1[q].z, s1);
            s0 = fmaf(av.w, x0[q].w, s0); s1 = fmaf(av.w, x1[q].w, s1);
        }
#pragma unroll
        for (int off = 16; off > 0; off >>= 1) {
            s0 += __shfl_xor_sync(0xffffffffu, s0, off);
            s1 += __shfl_xor_sync(0xffffffffu, s1, off);
        }
        if (lane == wi)     sc0 = s0;          // j0 window pos = wi
        if (lane == wi - 1) sc1 = s1;          // j1 window pos = wi-1
    }

    // masked softmax for both rows (21-wide windows at lanes 0..20)
    const int  lw0 = lo + lane;                // l of lane for j0's window
    const int  lw1 = lo + 1 + lane;            // l of lane for j1's window
    const bool va0 = (lane < 21) && (lw0 >= 0) && (lw0 < len);
    const bool va1 = (lane < 21) && (lw1 >= 0) && (lw1 < len) && (j1 < len);

    float v0 = va0 ? sc0 : -1e30f;
    float v1 = va1 ? sc1 : -1e30f;
    float m0v = v0, m1v = v1;
#pragma unroll
    for (int off = 16; off > 0; off >>= 1) {
        m0v = fmaxf(m0v, __shfl_xor_sync(0xffffffffu, m0v, off));
        m1v = fmaxf(m1v, __shfl_xor_sync(0xffffffffu, m1v, off));
    }
    float p0 = va0 ? expf(v0 - m0v) : 0.f;
    float p1 = va1 ? expf(v1 - m1v) : 0.f;
    float t0 = p0, t1 = p1;
#pragma unroll
    for (int off = 16; off > 0; off >>= 1) {
        t0 += __shfl_xor_sync(0xffffffffu, t0, off);
        t1 += __shfl_xor_sync(0xffffffffu, t1, off);
    }
    float pr0 = va0 ? (p0 / t0) : 0.f;         // j0 < len -> t0 > 0 when va0
    float pr1 = va1 ? (p1 / t1) : 0.f;

    // write both 110-column rows (warp-uniform trip count, predicated stores)
#pragma unroll
    for (int c0 = 0; c0 < 128; c0 += 32) {
        int c = c0 + lane;
        int w0 = c - lo;
        int w1 = c - lo - 1;
        int s0i = (w0 >= 0 && w0 < 32) ? w0 : 31;
        int s1i = (w1 >= 0 && w1 < 32) ? w1 : 31;
        float o0 = __shfl_sync(0xffffffffu, pr0, s0i);
        float o1 = __shfl_sync(0xffffffffu, pr1, s1i);
        if (w0 < 0 || w0 >= 32) o0 = 0.f;
        if (w1 < 0 || w1 >= 32) o1 = 0.f;
        if (c < 110) { orow0[c] = o0; orow1[c] = o1; }
    }
}

// ---------------------------------------------------------------------------
extern "C" void kernel_launch(void* const* d_in, const int* in_sizes, int n_in,
                              void* d_out, int out_size)
{
    const float* nf   = (const float*)d_in[0];
    const float* W    = (const float*)d_in[1];
    const int*   tlen = (const int*)d_in[2];
    float* out = (float*)d_out;

    static int attr_done = 0;
    if (!attr_done) {
        cudaFuncSetAttribute(edgeatt_gemm_hmma,
                             cudaFuncAttributeMaxDynamicSharedMemorySize, GEMM_SMEM);
        attr_done = 1;
    }

    scan_len<<<1, 1024>>>(tlen);
    fill_rowmap<<<B_SZ, 128>>>(tlen);
    split_A<<<(M_TOT * D_SZ / 4 + 255) / 256, 256>>>(nf);
    split_W<<<(D_SZ * D_SZ / 4 + 255) / 256, 256>>>(W);

    dim3 gg(D_SZ / 128, M_TOT / 128);    // (4, 880); dead tiles exit on Mc
    edgeatt_gemm_hmma<<<gg, 256, GEMM_SMEM>>>();

    dim3 gb(7, B_SZ);                    // 16 j per CTA (2 per warp)
    edgeatt_band_softmax<<<gb, 256>>>(nf, tlen, out);
}

// round 9
// speedup vs baseline: 3.2413x; 1.0755x over previous
#include <cuda_runtime.h>
#include <cuda_fp16.h>
#include <math.h>
#include <stdint.h>

#define B_SZ 1024
#define L_SZ 110
#define D_SZ 512
#define WPAST 10
#define WFUT 10
#define M_TOT (B_SZ * L_SZ)   // 112640

// ---------------- device scratch (allocation-guard-safe) -------------------
__device__ float  g_att[(size_t)M_TOT * D_SZ];     // compact att rows
__device__ __half g_Ahi[(size_t)M_TOT * D_SZ];     // compact hi rows
__device__ __half g_Alo[(size_t)M_TOT * D_SZ];     // compact lo rows
__device__ __half g_Whi[D_SZ * D_SZ];
__device__ __half g_Wlo[D_SZ * D_SZ];
__device__ int    g_cbase[B_SZ + 1];               // exclusive prefix of len; [B]=Mc
__device__ int    g_rowmap[M_TOT];                 // compact row -> absolute row

__device__ __forceinline__ uint32_t smem_u32(const void* p) {
    uint32_t a;
    asm("{ .reg .u64 t; cvta.to.shared.u64 t, %1; cvt.u32.u64 %0, t; }"
        : "=r"(a) : "l"(p));
    return a;
}

#define LDSM4(d, addr) \
    asm volatile("ldmatrix.sync.aligned.m8n8.x4.shared.b16 {%0,%1,%2,%3}, [%4];" \
        : "=r"((d)[0]), "=r"((d)[1]), "=r"((d)[2]), "=r"((d)[3]) : "r"(addr))

#define MMA_16816(d, a, b) \
    asm volatile("mma.sync.aligned.m16n8k16.row.col.f32.f16.f16.f32 " \
        "{%0,%1,%2,%3},{%4,%5,%6,%7},{%8,%9},{%0,%1,%2,%3};" \
        : "+f"((d)[0]), "+f"((d)[1]), "+f"((d)[2]), "+f"((d)[3]) \
        : "r"((a)[0]), "r"((a)[1]), "r"((a)[2]), "r"((a)[3]), \
          "r"((b)[0]), "r"((b)[1]))

// ---------------------------------------------------------------------------
// Prefix scan of text_len (one block, 1024 threads, Hillis-Steele)
// ---------------------------------------------------------------------------
__global__ __launch_bounds__(1024) void scan_len(const int* __restrict__ tlen) {
    __shared__ int s[B_SZ];
    const int t = threadIdx.x;
    s[t] = tlen[t];
    __syncthreads();
    for (int off = 1; off < B_SZ; off <<= 1) {
        int v = (t >= off) ? s[t - off] : 0;
        __syncthreads();
        s[t] += v;
        __syncthreads();
    }
    if (t == 0) g_cbase[0] = 0;
    g_cbase[t + 1] = s[t];
}

__global__ __launch_bounds__(128) void fill_rowmap(const int* __restrict__ tlen) {
    const int b    = blockIdx.x;
    const int len  = tlen[b];
    const int base = g_cbase[b];
    for (int l = threadIdx.x; l < len; l += 128)
        g_rowmap[base + l] = b * L_SZ + l;
}

// ---------------------------------------------------------------------------
// Gathered fp16 split: only compact (live) rows are converted.
// ---------------------------------------------------------------------------
__global__ __launch_bounds__(256) void split_A_compact(const float* __restrict__ src) {
    const int Mc = g_cbase[B_SZ];
    size_t i = (size_t)blockIdx.x * blockDim.x + threadIdx.x;   // float4 index
    int mc = (int)(i >> 7);                                     // /128 f4 per row
    if (mc >= Mc) return;
    int q = (int)(i & 127);
    const float* srow = src + (size_t)g_rowmap[mc] * D_SZ + q * 4;
    float4 v = *(const float4*)srow;
    __half h0 = __float2half_rn(v.x), h1 = __float2half_rn(v.y);
    __half h2 = __float2half_rn(v.z), h3 = __float2half_rn(v.w);
    __half l0 = __float2half_rn(v.x - __half2float(h0));
    __half l1 = __float2half_rn(v.y - __half2float(h1));
    __half l2 = __float2half_rn(v.z - __half2float(h2));
    __half l3 = __float2half_rn(v.w - __half2float(h3));
    ((__half2*)g_Ahi)[i * 2 + 0] = __halves2half2(h0, h1);
    ((__half2*)g_Ahi)[i * 2 + 1] = __halves2half2(h2, h3);
    ((__half2*)g_Alo)[i * 2 + 0] = __halves2half2(l0, l1);
    ((__half2*)g_Alo)[i * 2 + 1] = __halves2half2(l2, l3);
}
__global__ __launch_bounds__(256) void split_W(const float* __restrict__ src) {
    size_t i = (size_t)blockIdx.x * blockDim.x + threadIdx.x;
    const size_t n4 = (size_t)D_SZ * D_SZ / 4;
    if (i >= n4) return;
    float4 v = ((const float4*)src)[i];
    __half h0 = __float2half_rn(v.x), h1 = __float2half_rn(v.y);
    __half h2 = __float2half_rn(v.z), h3 = __float2half_rn(v.w);
    __half l0 = __float2half_rn(v.x - __half2float(h0));
    __half l1 = __float2half_rn(v.y - __half2float(h1));
    __half l2 = __float2half_rn(v.z - __half2float(h2));
    __half l3 = __float2half_rn(v.w - __half2float(h3));
    ((__half2*)g_Whi)[i * 2 + 0] = __halves2half2(h0, h1);
    ((__half2*)g_Whi)[i * 2 + 1] = __halves2half2(h2, h3);
    ((__half2*)g_Wlo)[i * 2 + 0] = __halves2half2(l0, l1);
    ((__half2*)g_Wlo)[i * 2 + 1] = __halves2half2(l2, l3);
}

// ---------------------------------------------------------------------------
// HMMA GEMM over COMPACT rows: att_c[mc, n] = sum_k A_c[mc, k] * W[n, k]
// CTA 128x128, 8 warps of 64x32. K chunks of 32 halves, 80B smem row stride,
// double buffer, LDG->reg->STS pipeline. 3 split-fp16 passes per k16 step.
// ---------------------------------------------------------------------------
#define KC 32
#define ROWB 80
#define TILE_B (128 * ROWB)
#define OFF_AHI 0
#define OFF_ALO (1 * TILE_B)
#define OFF_WHI (2 * TILE_B)
#define OFF_WLO (3 * TILE_B)
#define STAGE   (4 * TILE_B)
#define GEMM_SMEM (2 * STAGE)        // 81920
#define NCHUNK (D_SZ / KC)           // 16

__global__ __launch_bounds__(256) void edgeatt_gemm_hmma() {
    const int Mc = g_cbase[B_SZ];
    const int m0 = blockIdx.y * 128;
    if (m0 >= Mc) return;                       // dead tile: nothing to compute

    extern __shared__ char smg[];
    const uint32_t sb = smem_u32(smg);
    const int tid  = threadIdx.x;
    const int wid  = tid >> 5;
    const int lane = tid & 31;
    const int wm = wid >> 2;
    const int wn = wid & 3;
    const int n0 = blockIdx.x * 128;

    float acc[4][4][4];
#pragma unroll
    for (int i = 0; i < 4; i++)
#pragma unroll
        for (int j = 0; j < 4; j++)
#pragma unroll
            for (int q = 0; q < 4; q++) acc[i][j][q] = 0.f;

    size_t aoff[2], woff[2];
    int    soff[2];
#pragma unroll
    for (int i = 0; i < 2; i++) {
        int idx = tid + i * 256;
        int row = idx >> 2, ch = idx & 3;
        aoff[i] = (size_t)(m0 + row) * D_SZ + ch * 8;   // linear compact rows
        woff[i] = (size_t)(n0 + row) * D_SZ + ch * 8;
        soff[i] = row * ROWB + ch * 16;
    }

    uint4 vAh[2], vAl[2], vWh[2], vWl[2];
#pragma unroll
    for (int i = 0; i < 2; i++) {
        vAh[i] = *(const uint4*)(g_Ahi + aoff[i]);
        vAl[i] = *(const uint4*)(g_Alo + aoff[i]);
        vWh[i] = *(const uint4*)(g_Whi + woff[i]);
        vWl[i] = *(const uint4*)(g_Wlo + woff[i]);
    }
#pragma unroll
    for (int i = 0; i < 2; i++) {
        *(uint4*)(smg + OFF_AHI + soff[i]) = vAh[i];
        *(uint4*)(smg + OFF_ALO + soff[i]) = vAl[i];
        *(uint4*)(smg + OFF_WHI + soff[i]) = vWh[i];
        *(uint4*)(smg + OFF_WLO + soff[i]) = vWl[i];
    }
    __syncthreads();

    const int g = lane >> 3, r = lane & 7;
    const int arow = wm * 64 + ((g & 1) << 3) + r;
    const int brow = wn * 32 + ((g >> 1) << 3) + r;
    const int akc  = (g >> 1);
    const int bkc  = (g & 1);

    for (int c = 0; c < NCHUNK; c++) {
        const int buf = c & 1;
        if (c + 1 < NCHUNK) {
            size_t kadd = (size_t)(c + 1) * KC;
#pragma unroll
            for (int i = 0; i < 2; i++) {
                vAh[i] = *(const uint4*)(g_Ahi + aoff[i] + kadd);
                vAl[i] = *(const uint4*)(g_Alo + aoff[i] + kadd);
                vWh[i] = *(const uint4*)(g_Whi + woff[i] + kadd);
                vWl[i] = *(const uint4*)(g_Wlo + woff[i] + kadd);
            }
        }

        const uint32_t abase = sb + buf * STAGE;
#pragma unroll
        for (int ks = 0; ks < 2; ks++) {
            uint32_t ah[4][4], al[4][4], bh[2][4], bl[2][4];
#pragma unroll
            for (int mt = 0; mt < 4; mt++) {
                uint32_t ad = abase + OFF_AHI + (arow + mt * 16) * ROWB
                            + (ks * 2 + akc) * 16;
                LDSM4(ah[mt], ad);
                LDSM4(al[mt], ad + (OFF_ALO - OFF_AHI));
            }
#pragma unroll
            for (int bt = 0; bt < 2; bt++) {
                uint32_t bd = abase + OFF_WHI + (brow + bt * 16) * ROWB
                            + (ks * 2 + bkc) * 16;
                LDSM4(bh[bt], bd);
                LDSM4(bl[bt], bd + (OFF_WLO - OFF_WHI));
            }
#pragma unroll
            for (int mt = 0; mt < 4; mt++)
#pragma unroll
                for (int nt = 0; nt < 4; nt++) {
                    const int bt = nt >> 1, h = (nt & 1) * 2;
                    MMA_16816(acc[mt][nt], ah[mt], &bh[bt][h]);
                    MMA_16816(acc[mt][nt], ah[mt], &bl[bt][h]);
                    MMA_16816(acc[mt][nt], al[mt], &bh[bt][h]);
                }
        }

        if (c + 1 < NCHUNK) {
            char* p = smg + (buf ^ 1) * STAGE;
#pragma unroll
            for (int i = 0; i < 2; i++) {
                *(uint4*)(p + OFF_AHI + soff[i]) = vAh[i];
                *(uint4*)(p + OFF_ALO + soff[i]) = vAl[i];
                *(uint4*)(p + OFF_WHI + soff[i]) = vWh[i];
                *(uint4*)(p + OFF_WLO + soff[i]) = vWl[i];
            }
        }
        __syncthreads();
    }

    // epilogue: compact-row store, predicated on Mc
    const int er = lane >> 2, ec = (lane & 3) * 2;
#pragma unroll
    for (int mt = 0; mt < 4; mt++) {
        const int row = m0 + wm * 64 + mt * 16 + er;
#pragma unroll
        for (int nt = 0; nt < 4; nt++) {
            const int col = n0 + wn * 32 + nt * 8 + ec;
            if (row < Mc)
                *(float2*)&g_att[(size_t)row * D_SZ + col] =
                    make_float2(acc[mt][nt][0], acc[mt][nt][1]);
            if (row + 8 < Mc)
                *(float2*)&g_att[(size_t)(row + 8) * D_SZ + col] =
                    make_float2(acc[mt][nt][2], acc[mt][nt][3]);
        }
    }
}

// ---------------------------------------------------------------------------
// Band + softmax: one warp handles FOUR adjacent j rows (j0 % 4 == 0).
// One pass over the 24-row union of att rows feeds all four dot sets.
// att is compact: row (b, l) lives at g_att[(cbase[b] + l) * 512].
// ---------------------------------------------------------------------------
#define NJ 4
#define UNION_W (WPAST + WFUT + NJ)   // 24

__global__ __launch_bounds__(256) void edgeatt_band_softmax(
    const float* __restrict__ nf,     // [B, L, 512]
    const int*   __restrict__ tlen,   // [B]
    float*       __restrict__ out)    // [B, L, 110]
{
    const int b    = blockIdx.y;
    const int warp = threadIdx.x >> 5;
    const int lane = threadIdx.x & 31;
    const int j0   = blockIdx.x * (8 * NJ) + warp * NJ;
    if (j0 >= L_SZ) return;

    const int len  = tlen[b];
    const int base = g_cbase[b];

    if (j0 >= len) {                           // all NJ rows fully masked
#pragma unroll
        for (int r = 0; r < NJ; r++) {
            int j = j0 + r;
            if (j >= L_SZ) break;              // warp-uniform
            float* orow = out + ((size_t)b * L_SZ + j) * 110;
#pragma unroll
            for (int c0 = 0; c0 < 128; c0 += 32) {
                int c = c0 + lane;
                if (c < 110) orow[c] = 0.f;
            }
        }
        return;
    }

    // feature rows: lane owns k = lane*16 .. lane*16+15 for each of 4 j's
    float4 x[NJ][4];
#pragma unroll
    for (int r = 0; r < NJ; r++) {
        int j = min(j0 + r, L_SZ - 1);         // clamp; invalid rows masked later
        const float* xr = nf + ((size_t)b * L_SZ + j) * D_SZ;
#pragma unroll
        for (int q = 0; q < 4; q++)
            x[r][q] = *(const float4*)&xr[lane * 16 + q * 4];
    }

    const int lo = j0 - WPAST;                 // union start
    float sc[NJ] = {0.f, 0.f, 0.f, 0.f};       // lane w: score of window pos w

#pragma unroll 1
    for (int wi = 0; wi < UNION_W; wi++) {
        int l = lo + wi;                       // warp-uniform
        if (l < 0 || l >= len) continue;
        const float* ar = g_att + ((size_t)(base + l)) * D_SZ;
        float s0 = 0.f, s1 = 0.f, s2 = 0.f, s3 = 0.f;
#pragma unroll
        for (int q = 0; q < 4; q++) {
            float4 av = *(const float4*)&ar[lane * 16 + q * 4];
            s0 = fmaf(av.x, x[0][q].x, s0); s1 = fmaf(av.x, x[1][q].x, s1);
            s2 = fmaf(av.x, x[2][q].x, s2); s3 = fmaf(av.x, x[3][q].x, s3);
            s0 = fmaf(av.y, x[0][q].y, s0); s1 = fmaf(av.y, x[1][q].y, s1);
            s2 = fmaf(av.y, x[2][q].y, s2); s3 = fmaf(av.y, x[3][q].y, s3);
            s0 = fmaf(av.z, x[0][q].z, s0); s1 = fmaf(av.z, x[1][q].z, s1);
            s2 = fmaf(av.z, x[2][q].z, s2); s3 = fmaf(av.z, x[3][q].z, s3);
            s0 = fmaf(av.w, x[0][q].w, s0); s1 = fmaf(av.w, x[1][q].w, s1);
            s2 = fmaf(av.w, x[2][q].w, s2); s3 = fmaf(av.w, x[3][q].w, s3);
        }
#pragma unroll
        for (int off = 16; off > 0; off >>= 1) {
            s0 += __shfl_xor_sync(0xffffffffu, s0, off);
            s1 += __shfl_xor_sync(0xffffffffu, s1, off);
            s2 += __shfl_xor_sync(0xffffffffu, s2, off);
            s3 += __shfl_xor_sync(0xffffffffu, s3, off);
        }
        if (lane == wi)     sc[0] = s0;        // j0+r window pos = wi - r
        if (lane == wi - 1) sc[1] = s1;
        if (lane == wi - 2) sc[2] = s2;
        if (lane == wi - 3) sc[3] = s3;
    }

    // masked softmax for all rows (21-wide windows at lanes 0..20)
    float pr[NJ];
#pragma unroll
    for (int r = 0; r < NJ; r++) {
        int  j   = j0 + r;
        int  lw  = lo + r + lane;              // l of this lane in row r's window
        bool va  = (lane < 21) && (lw >= 0) && (lw < len) && (j < len) && (j < L_SZ);
        float v = va ? sc[r] : -1e30f;
        float m = v;
#pragma unroll
        for (int off = 16; off > 0; off >>= 1)
            m = fmaxf(m, __shfl_xor_sync(0xffffffffu, m, off));
        float p = va ? expf(v - m) : 0.f;
        float t = p;
#pragma unroll
        for (int off = 16; off > 0; off >>= 1)
            t += __shfl_xor_sync(0xffffffffu, t, off);
        pr[r] = va ? (p / t) : 0.f;            // va implies j<len -> t>0
    }

    // write all rows (warp-uniform trip counts, predicated stores)
#pragma unroll
    for (int r = 0; r < NJ; r++) {
        int j = j0 + r;
        if (j >= L_SZ) break;                  // warp-uniform
        float* orow = out + ((size_t)b * L_SZ + j) * 110;
#pragma unroll
        for (int c0 = 0; c0 < 128; c0 += 32) {
            int c  = c0 + lane;
            int w  = c - lo - r;               // window index of column c
            int si = (w >= 0 && w < 32) ? w : 31;
            float val = __shfl_sync(0xffffffffu, pr[r], si);
            if (w < 0 || w >= 32) val = 0.f;
            if (c < 110) orow[c] = val;
        }
    }
}

// ---------------------------------------------------------------------------
extern "C" void kernel_launch(void* const* d_in, const int* in_sizes, int n_in,
                              void* d_out, int out_size)
{
    const float* nf   = (const float*)d_in[0];
    const float* W    = (const float*)d_in[1];
    const int*   tlen = (const int*)d_in[2];
    float* out = (float*)d_out;

    static int attr_done = 0;
    if (!attr_done) {
        cudaFuncSetAttribute(edgeatt_gemm_hmma,
                             cudaFuncAttributeMaxDynamicSharedMemorySize, GEMM_SMEM);
        attr_done = 1;
    }

    scan_len<<<1, 1024>>>(tlen);
    fill_rowmap<<<B_SZ, 128>>>(tlen);
    split_W<<<(D_SZ * D_SZ / 4 + 255) / 256, 256>>>(W);
    split_A_compact<<<(M_TOT * D_SZ / 4 + 255) / 256, 256>>>(nf);

    dim3 gg(D_SZ / 128, M_TOT / 128);    // (4, 880); dead tiles exit on Mc
    edgeatt_gemm_hmma<<<gg, 256, GEMM_SMEM>>>();

    dim3 gb((L_SZ + 8 * NJ - 1) / (8 * NJ), B_SZ);   // (4, 1024)
    edgeatt_band_softmax<<<gb, 256>>>(nf, tlen, out);
}

// round 11
// speedup vs baseline: 3.5800x; 1.1045x over previous
#include <cuda_runtime.h>
#include <cuda_fp16.h>
#include <math.h>
#include <stdint.h>

#define B_SZ 1024
#define L_SZ 110
#define D_SZ 512
#define WPAST 10
#define WFUT 10
#define M_TOT (B_SZ * L_SZ)   // 112640

// ---------------- device scratch (allocation-guard-safe) -------------------
__device__ float  g_att[(size_t)M_TOT * D_SZ];     // compact att rows
__device__ __half g_Ahi[(size_t)M_TOT * D_SZ];     // compact hi rows
__device__ __half g_Alo[(size_t)M_TOT * D_SZ];     // compact lo rows
__device__ __half g_Whi[D_SZ * D_SZ];
__device__ __half g_Wlo[D_SZ * D_SZ];
__device__ int    g_cbase[B_SZ + 1];               // exclusive prefix of len; [B]=Mc
__device__ int    g_rowmap[M_TOT];                 // compact row -> absolute row

__device__ __forceinline__ uint32_t smem_u32(const void* p) {
    uint32_t a;
    asm("{ .reg .u64 t; cvta.to.shared.u64 t, %1; cvt.u32.u64 %0, t; }"
        : "=r"(a) : "l"(p));
    return a;
}

#define LDSM4(d, addr) \
    asm volatile("ldmatrix.sync.aligned.m8n8.x4.shared.b16 {%0,%1,%2,%3}, [%4];" \
        : "=r"((d)[0]), "=r"((d)[1]), "=r"((d)[2]), "=r"((d)[3]) : "r"(addr))

#define MMA_16816(d, a, b) \
    asm volatile("mma.sync.aligned.m16n8k16.row.col.f32.f16.f16.f32 " \
        "{%0,%1,%2,%3},{%4,%5,%6,%7},{%8,%9},{%0,%1,%2,%3};" \
        : "+f"((d)[0]), "+f"((d)[1]), "+f"((d)[2]), "+f"((d)[3]) \
        : "r"((a)[0]), "r"((a)[1]), "r"((a)[2]), "r"((a)[3]), \
          "r"((b)[0]), "r"((b)[1]))

#define CP_ASYNC16(saddr, gptr) \
    asm volatile("cp.async.cg.shared.global [%0], [%1], 16;" \
                 :: "r"(saddr), "l"(gptr) : "memory")
#define CP_COMMIT() asm volatile("cp.async.commit_group;" ::: "memory")
#define CP_WAIT1()  asm volatile("cp.async.wait_group 1;" ::: "memory")
#define CP_WAIT0()  asm volatile("cp.async.wait_group 0;" ::: "memory")

// ---------------------------------------------------------------------------
// Prefix scan of text_len (one block, 1024 threads, Hillis-Steele)
// ---------------------------------------------------------------------------
__global__ __launch_bounds__(1024) void scan_len(const int* __restrict__ tlen) {
    __shared__ int s[B_SZ];
    const int t = threadIdx.x;
    s[t] = tlen[t];
    __syncthreads();
    for (int off = 1; off < B_SZ; off <<= 1) {
        int v = (t >= off) ? s[t - off] : 0;
        __syncthreads();
        s[t] += v;
        __syncthreads();
    }
    if (t == 0) g_cbase[0] = 0;
    g_cbase[t + 1] = s[t];
}

__global__ __launch_bounds__(128) void fill_rowmap(const int* __restrict__ tlen) {
    const int b    = blockIdx.x;
    const int len  = tlen[b];
    const int base = g_cbase[b];
    for (int l = threadIdx.x; l < len; l += 128)
        g_rowmap[base + l] = b * L_SZ + l;
}

// ---------------------------------------------------------------------------
// Gathered fp16 split: only compact (live) rows; 2 float4 per thread.
// ---------------------------------------------------------------------------
__global__ __launch_bounds__(256) void split_A_compact(const float* __restrict__ src) {
    const int Mc = g_cbase[B_SZ];
    size_t i = (size_t)blockIdx.x * blockDim.x + threadIdx.x;   // 32B-pair index
    int mc = (int)(i >> 6);                                     // 64 pairs per row
    if (mc >= Mc) return;
    int q = (int)(i & 63) * 2;                                  // float4 idx in row
    const float4* srow = (const float4*)(src + (size_t)g_rowmap[mc] * D_SZ) + q;
#pragma unroll
    for (int t = 0; t < 2; t++) {
        float4 v = srow[t];
        __half h0 = __float2half_rn(v.x), h1 = __float2half_rn(v.y);
        __half h2 = __float2half_rn(v.z), h3 = __float2half_rn(v.w);
        __half l0 = __float2half_rn(v.x - __half2float(h0));
        __half l1 = __float2half_rn(v.y - __half2float(h1));
        __half l2 = __float2half_rn(v.z - __half2float(h2));
        __half l3 = __float2half_rn(v.w - __half2float(h3));
        size_t o = (size_t)mc * 256 + (q + t) * 2;              // half2 index
        ((__half2*)g_Ahi)[o + 0] = __halves2half2(h0, h1);
        ((__half2*)g_Ahi)[o + 1] = __halves2half2(h2, h3);
        ((__half2*)g_Alo)[o + 0] = __halves2half2(l0, l1);
        ((__half2*)g_Alo)[o + 1] = __halves2half2(l2, l3);
    }
}
__global__ __launch_bounds__(256) void split_W(const float* __restrict__ src) {
    size_t i = (size_t)blockIdx.x * blockDim.x + threadIdx.x;
    const size_t n4 = (size_t)D_SZ * D_SZ / 4;
    if (i >= n4) return;
    float4 v = ((const float4*)src)[i];
    __half h0 = __float2half_rn(v.x), h1 = __float2half_rn(v.y);
    __half h2 = __float2half_rn(v.z), h3 = __float2half_rn(v.w);
    __half l0 = __float2half_rn(v.x - __half2float(h0));
    __half l1 = __float2half_rn(v.y - __half2float(h1));
    __half l2 = __float2half_rn(v.z - __half2float(h2));
    __half l3 = __float2half_rn(v.w - __half2float(h3));
    ((__half2*)g_Whi)[i * 2 + 0] = __halves2half2(h0, h1);
    ((__half2*)g_Whi)[i * 2 + 1] = __halves2half2(h2, h3);
    ((__half2*)g_Wlo)[i * 2 + 0] = __halves2half2(l0, l1);
    ((__half2*)g_Wlo)[i * 2 + 1] = __halves2half2(l2, l3);
}

// ---------------------------------------------------------------------------
// HMMA GEMM over COMPACT rows: att_c[mc, n] = sum_k A_c[mc, k] * W[n, k]
// CTA 128x256, 8 warps of 64x64. K chunks of 32 halves, 80B smem row stride,
// cp.async double buffer. 3 split-fp16 passes per k16 step.
// ---------------------------------------------------------------------------
#define KC 32
#define ROWB 80
#define A_T (128 * ROWB)             // 10240
#define W_T (256 * ROWB)             // 20480
#define OFF_AHI 0
#define OFF_ALO A_T
#define OFF_WHI (2 * A_T)
#define OFF_WLO (2 * A_T + W_T)
#define STAGE (2 * A_T + 2 * W_T)    // 61440
#define GEMM_SMEM (2 * STAGE)        // 122880
#define NCHUNK (D_SZ / KC)           // 16

__global__ __launch_bounds__(256, 1) void edgeatt_gemm_hmma() {
    const int Mc = g_cbase[B_SZ];
    const int m0 = blockIdx.y * 128;
    if (m0 >= Mc) return;                       // dead tile

    extern __shared__ char smg[];
    const uint32_t sb = smem_u32(smg);
    const int tid  = threadIdx.x;
    const int wid  = tid >> 5;
    const int lane = tid & 31;
    const int wm = wid >> 2;                    // 0..1 -> m offset wm*64
    const int wn = wid & 3;                     // 0..3 -> n offset wn*64
    const int n0 = blockIdx.x * 256;

    float acc[4][8][4];
#pragma unroll
    for (int i = 0; i < 4; i++)
#pragma unroll
        for (int j = 0; j < 8; j++)
#pragma unroll
            for (int q = 0; q < 4; q++) acc[i][j][q] = 0.f;

    // load mappings: A 512 16B-chunks (2/thread), W 1024 (4/thread)
    size_t aoff[2]; int asf[2];
#pragma unroll
    for (int i = 0; i < 2; i++) {
        int idx = tid + i * 256, row = idx >> 2, ch = idx & 3;
        aoff[i] = (size_t)(m0 + row) * D_SZ + ch * 8;
        asf[i]  = row * ROWB + ch * 16;
    }
    size_t woff[4]; int wsf[4];
#pragma unroll
    for (int i = 0; i < 4; i++) {
        int idx = tid + i * 256, row = idx >> 2, ch = idx & 3;
        woff[i] = (size_t)(n0 + row) * D_SZ + ch * 8;
        wsf[i]  = row * ROWB + ch * 16;
    }

    auto issue = [&](int c, int buf) {
        const uint32_t s0 = sb + buf * STAGE;
        const size_t ka = (size_t)c * KC;
#pragma unroll
        for (int i = 0; i < 2; i++) {
            CP_ASYNC16(s0 + OFF_AHI + asf[i], g_Ahi + aoff[i] + ka);
            CP_ASYNC16(s0 + OFF_ALO + asf[i], g_Alo + aoff[i] + ka);
        }
#pragma unroll
        for (int i = 0; i < 4; i++) {
            CP_ASYNC16(s0 + OFF_WHI + wsf[i], g_Whi + woff[i] + ka);
            CP_ASYNC16(s0 + OFF_WLO + wsf[i], g_Wlo + woff[i] + ka);
        }
        CP_COMMIT();
    };

    issue(0, 0);

    const int g = lane >> 3, r = lane & 7;
    const int arow = wm * 64 + ((g & 1) << 3) + r;
    const int brow = wn * 64 + ((g >> 1) << 3) + r;
    const int akc  = (g >> 1);
    const int bkc  = (g & 1);

    for (int c = 0; c < NCHUNK; c++) {
        const int buf = c & 1;
        if (c + 1 < NCHUNK) { issue(c + 1, buf ^ 1); CP_WAIT1(); }
        else                { CP_WAIT0(); }
        __syncthreads();

        const uint32_t abase = sb + buf * STAGE;
#pragma unroll
        for (int ks = 0; ks < 2; ks++) {
            uint32_t ah[4][4], al[4][4], bh[4][4], bl[4][4];
#pragma unroll
            for (int mt = 0; mt < 4; mt++) {
                uint32_t ad = abase + OFF_AHI + (arow + mt * 16) * ROWB
                            + (ks * 2 + akc) * 16;
                LDSM4(ah[mt], ad);
                LDSM4(al[mt], ad + (OFF_ALO - OFF_AHI));
            }
#pragma unroll
            for (int bt = 0; bt < 4; bt++) {
                uint32_t bd = abase + OFF_WHI + (brow + bt * 16) * ROWB
                            + (ks * 2 + bkc) * 16;
                LDSM4(bh[bt], bd);
                LDSM4(bl[bt], bd + (OFF_WLO - OFF_WHI));
            }
#pragma unroll
            for (int mt = 0; mt < 4; mt++)
#pragma unroll
                for (int nt = 0; nt < 8; nt++) {
                    const int bt = nt >> 1, h = (nt & 1) * 2;
                    MMA_16816(acc[mt][nt], ah[mt], &bh[bt][h]);
                    MMA_16816(acc[mt][nt], ah[mt], &bl[bt][h]);
                    MMA_16816(acc[mt][nt], al[mt], &bh[bt][h]);
                }
        }
        __syncthreads();
    }

    // epilogue: compact-row store, predicated on Mc
    const int er = lane >> 2, ec = (lane & 3) * 2;
#pragma unroll
    for (int mt = 0; mt < 4; mt++) {
        const int row = m0 + wm * 64 + mt * 16 + er;
#pragma unroll
        for (int nt = 0; nt < 8; nt++) {
            const int col = n0 + wn * 64 + nt * 8 + ec;
            if (row < Mc)
                *(float2*)&g_att[(size_t)row * D_SZ + col] =
                    make_float2(acc[mt][nt][0], acc[mt][nt][1]);
            if (row + 8 < Mc)
                *(float2*)&g_att[(size_t)(row + 8) * D_SZ + col] =
                    make_float2(acc[mt][nt][2], acc[mt][nt][3]);
        }
    }
}

// ---------------------------------------------------------------------------
// Band + softmax: one warp handles FOUR adjacent j rows. Unchanged from R8.
// ---------------------------------------------------------------------------
#define NJ 4
#define UNION_W (WPAST + WFUT + NJ)   // 24

__global__ __launch_bounds__(256) void edgeatt_band_softmax(
    const float* __restrict__ nf,     // [B, L, 512]
    const int*   __restrict__ tlen,   // [B]
    float*       __restrict__ out)    // [B, L, 110]
{
    const int b    = blockIdx.y;
    const int warp = threadIdx.x >> 5;
    const int lane = threadIdx.x & 31;
    const int j0   = blockIdx.x * (8 * NJ) + warp * NJ;
    if (j0 >= L_SZ) return;

    const int len  = tlen[b];
    const int base = g_cbase[b];

    if (j0 >= len) {
#pragma unroll
        for (int r = 0; r < NJ; r++) {
            int j = j0 + r;
            if (j >= L_SZ) break;
            float* orow = out + ((size_t)b * L_SZ + j) * 110;
#pragma unroll
            for (int c0 = 0; c0 < 128; c0 += 32) {
                int c = c0 + lane;
                if (c < 110) orow[c] = 0.f;
            }
        }
        return;
    }

    float4 x[NJ][4];
#pragma unroll
    for (int r = 0; r < NJ; r++) {
        int j = min(j0 + r, L_SZ - 1);
        const float* xr = nf + ((size_t)b * L_SZ + j) * D_SZ;
#pragma unroll
        for (int q = 0; q < 4; q++)
            x[r][q] = *(const float4*)&xr[lane * 16 + q * 4];
    }

    const int lo = j0 - WPAST;
    float sc[NJ] = {0.f, 0.f, 0.f, 0.f};

#pragma unroll 1
    for (int wi = 0; wi < UNION_W; wi++) {
        int l = lo + wi;
        if (l < 0 || l >= len) continue;
        const float* ar = g_att + ((size_t)(base + l)) * D_SZ;
        float s0 = 0.f, s1 = 0.f, s2 = 0.f, s3 = 0.f;
#pragma unroll
        for (int q = 0; q < 4; q++) {
            float4 av = *(const float4*)&ar[lane * 16 + q * 4];
            s0 = fmaf(av.x, x[0][q].x, s0); s1 = fmaf(av.x, x[1][q].x, s1);
            s2 = fmaf(av.x, x[2][q].x, s2); s3 = fmaf(av.x, x[3][q].x, s3);
            s0 = fmaf(av.y, x[0][q].y, s0); s1 = fmaf(av.y, x[1][q].y, s1);
            s2 = fmaf(av.y, x[2][q].y, s2); s3 = fmaf(av.y, x[3][q].y, s3);
            s0 = fmaf(av.z, x[0][q].z, s0); s1 = fmaf(av.z, x[1][q].z, s1);
            s2 = fmaf(av.z, x[2][q].z, s2); s3 = fmaf(av.z, x[3][q].z, s3);
            s0 = fmaf(av.w, x[0][q].w, s0); s1 = fmaf(av.w, x[1][q].w, s1);
            s2 = fmaf(av.w, x[2][q].w, s2); s3 = fmaf(av.w, x[3][q].w, s3);
        }
#pragma unroll
        for (int off = 16; off > 0; off >>= 1) {
            s0 += __shfl_xor_sync(0xffffffffu, s0, off);
            s1 += __shfl_xor_sync(0xffffffffu, s1, off);
            s2 += __shfl_xor_sync(0xffffffffu, s2, off);
            s3 += __shfl_xor_sync(0xffffffffu, s3, off);
        }
        if (lane == wi)     sc[0] = s0;
        if (lane == wi - 1) sc[1] = s1;
        if (lane == wi - 2) sc[2] = s2;
        if (lane == wi - 3) sc[3] = s3;
    }

    float pr[NJ];
#pragma unroll
    for (int r = 0; r < NJ; r++) {
        int  j  = j0 + r;
        int  lw = lo + r + lane;
        bool va = (lane < 21) && (lw >= 0) && (lw < len) && (j < len) && (j < L_SZ);
        float v = va ? sc[r] : -1e30f;
        float m = v;
#pragma unroll
        for (int off = 16; off > 0; off >>= 1)
            m = fmaxf(m, __shfl_xor_sync(0xffffffffu, m, off));
        float p = va ? expf(v - m) : 0.f;
        float t = p;
#pragma unroll
        for (int off = 16; off > 0; off >>= 1)
            t += __shfl_xor_sync(0xffffffffu, t, off);
        pr[r] = va ? (p / t) : 0.f;
    }

#pragma unroll
    for (int r = 0; r < NJ; r++) {
        int j = j0 + r;
        if (j >= L_SZ) break;
        float* orow = out + ((size_t)b * L_SZ + j) * 110;
#pragma unroll
        for (int c0 = 0; c0 < 128; c0 += 32) {
            int c  = c0 + lane;
            int w  = c - lo - r;
            int si = (w >= 0 && w < 32) ? w : 31;
            float val = __shfl_sync(0xffffffffu, pr[r], si);
            if (w < 0 || w >= 32) val = 0.f;
            if (c < 110) orow[c] = val;
        }
    }
}

// ---------------------------------------------------------------------------
extern "C" void kernel_launch(void* const* d_in, const int* in_sizes, int n_in,
                              void* d_out, int out_size)
{
    const float* nf   = (const float*)d_in[0];
    const float* W    = (const float*)d_in[1];
    const int*   tlen = (const int*)d_in[2];
    float* out = (float*)d_out;

    static int attr_done = 0;
    if (!attr_done) {
        cudaFuncSetAttribute(edgeatt_gemm_hmma,
                             cudaFuncAttributeMaxDynamicSharedMemorySize, GEMM_SMEM);
        attr_done = 1;
    }

    scan_len<<<1, 1024>>>(tlen);
    fill_rowmap<<<B_SZ, 128>>>(tlen);
    split_W<<<(D_SZ * D_SZ / 4 + 255) / 256, 256>>>(W);
    split_A_compact<<<((size_t)M_TOT * 64 + 255) / 256, 256>>>(nf);

    dim3 gg(D_SZ / 256, M_TOT / 128);    // (2, 880); dead tiles exit on Mc
    edgeatt_gemm_hmma<<<gg, 256, GEMM_SMEM>>>();

    dim3 gb((L_SZ + 8 * NJ - 1) / (8 * NJ), B_SZ);   // (4, 1024)
    edgeatt_band_softmax<<<gb, 256>>>(nf, tlen, out);
}